// round 13
// baseline (speedup 1.0000x reference)
#include <cuda_runtime.h>
#include <cuda_bf16.h>

#define BB   64
#define MM   64
#define NN   64
#define OUT  512

#define U_TILE  16
#define V_TILE  128
#define THREADS 128
#define CHUNK   4                  // u-rows staged per copy
#define ROWF    (V_TILE * 3)       // 384 floats per staged u-row

__global__ __launch_bounds__(THREADS, 11) void surfeval_kernel(
    const float4* __restrict__ ctrl4,   // (B, M, N) float4 (xyzw)
    const float4* __restrict__ Nu4,     // (OUT)
    const float4* __restrict__ Nv4,     // (OUT)
    const int* __restrict__ iu,         // (OUT,4) int32
    const int* __restrict__ iv,         // (OUT,4) int32
    float* __restrict__ out)            // (B, OUT, OUT, 3)
{
    __shared__ float  s_buf[2][CHUNK * ROWF];   // 2 x 6KB staging
    __shared__ float4 s_Nu[U_TILE];
    __shared__ int    s_row0[U_TILE];

    const int tid = threadIdx.x;
    const int vt  = blockIdx.x;
    const int ut  = blockIdx.y;
    const int b   = blockIdx.z;

    const int u_lo = ut * U_TILE;

    if (tid < U_TILE) {
        s_Nu[tid]   = __ldg(&Nu4[u_lo + tid]);
        s_row0[tid] = __ldg(&iu[(u_lo + tid) * 4]);
    }
    __syncthreads();

    const int v = vt * V_TILE + tid;
    const float4 nv = __ldg(&Nv4[v]);
    const int iv0 = __ldg(&iv[v * 4]);

    const float4* cb = ctrl4 + ((size_t)b * MM * NN) + iv0;

    // gmem base for this block's v-tile at u_lo (floats)
    float* gbase = out + (((size_t)b * OUT + u_lo) * OUT + vt * V_TILE) * 3;

    float4 rd0, rd1, rd2, rd3;
    int cur_row = -1;
    int buf = 0;

    #pragma unroll 1
    for (int c0 = 0; c0 < U_TILE; c0 += CHUNK) {
        // ---- compute CHUNK u-rows into s_buf[buf] ----
        float* sb = s_buf[buf] + tid * 3;
        #pragma unroll
        for (int uc = 0; uc < CHUNK; ++uc) {
            const int uo = c0 + uc;
            const int r0 = s_row0[uo];
            if (r0 != cur_row) {          // warp-uniform branch
                cur_row = r0;
                const float4* p = cb + (size_t)r0 * NN;
                float4 c0v = p[0], c1v = p[1], c2v = p[2], c3v = p[3];
                rd0.x = nv.x*c0v.x + nv.y*c1v.x + nv.z*c2v.x + nv.w*c3v.x;
                rd0.y = nv.x*c0v.y + nv.y*c1v.y + nv.z*c2v.y + nv.w*c3v.y;
                rd0.z = nv.x*c0v.z + nv.y*c1v.z + nv.z*c2v.z + nv.w*c3v.z;
                rd0.w = nv.x*c0v.w + nv.y*c1v.w + nv.z*c2v.w + nv.w*c3v.w;
                p += NN;
                c0v = p[0]; c1v = p[1]; c2v = p[2]; c3v = p[3];
                rd1.x = nv.x*c0v.x + nv.y*c1v.x + nv.z*c2v.x + nv.w*c3v.x;
                rd1.y = nv.x*c0v.y + nv.y*c1v.y + nv.z*c2v.y + nv.w*c3v.y;
                rd1.z = nv.x*c0v.z + nv.y*c1v.z + nv.z*c2v.z + nv.w*c3v.z;
                rd1.w = nv.x*c0v.w + nv.y*c1v.w + nv.z*c2v.w + nv.w*c3v.w;
                p += NN;
                c0v = p[0]; c1v = p[1]; c2v = p[2]; c3v = p[3];
                rd2.x = nv.x*c0v.x + nv.y*c1v.x + nv.z*c2v.x + nv.w*c3v.x;
                rd2.y = nv.x*c0v.y + nv.y*c1v.y + nv.z*c2v.y + nv.w*c3v.y;
                rd2.z = nv.x*c0v.z + nv.y*c1v.z + nv.z*c2v.z + nv.w*c3v.z;
                rd2.w = nv.x*c0v.w + nv.y*c1v.w + nv.z*c2v.w + nv.w*c3v.w;
                p += NN;
                c0v = p[0]; c1v = p[1]; c2v = p[2]; c3v = p[3];
                rd3.x = nv.x*c0v.x + nv.y*c1v.x + nv.z*c2v.x + nv.w*c3v.x;
                rd3.y = nv.x*c0v.y + nv.y*c1v.y + nv.z*c2v.y + nv.w*c3v.y;
                rd3.z = nv.x*c0v.z + nv.y*c1v.z + nv.z*c2v.z + nv.w*c3v.z;
                rd3.w = nv.x*c0v.w + nv.y*c1v.w + nv.z*c2v.w + nv.w*c3v.w;
            }

            const float4 nu = s_Nu[uo];
            float4 acc;
            acc.x = nu.x*rd0.x + nu.y*rd1.x + nu.z*rd2.x + nu.w*rd3.x;
            acc.y = nu.x*rd0.y + nu.y*rd1.y + nu.z*rd2.y + nu.w*rd3.y;
            acc.z = nu.x*rd0.z + nu.y*rd1.z + nu.z*rd2.z + nu.w*rd3.z;
            acc.w = nu.x*rd0.w + nu.y*rd1.w + nu.z*rd2.w + nu.w*rd3.w;

            const float inv = __fdividef(1.0f, acc.w);
            // 12B-stride STS: bank = 3*lane mod 32, conflict-free
            sb[uc * ROWF + 0] = acc.x * inv;
            sb[uc * ROWF + 1] = acc.y * inv;
            sb[uc * ROWF + 2] = acc.z * inv;
        }

        __syncthreads();   // staging of this buffer complete (also fences prior copy of this buffer — see double-buffer ordering)

        // ---- dense copy: CHUNK*ROWF = 1536 floats = 384 float4, 3 per thread ----
        float* gdst = gbase + (size_t)c0 * (OUT * 3);
        const float* sbuf = s_buf[buf];
        #pragma unroll
        for (int k = 0; k < 3; ++k) {
            const int j   = tid + THREADS * k;   // 0..383
            const int row = j / 96;              // 96 float4 per u-row
            const int col = j - row * 96;
            const float4 val = *(const float4*)(sbuf + row * ROWF + col * 4);
            *(float4*)(gdst + (size_t)row * (OUT * 3) + col * 4) = val;
        }

        buf ^= 1;
    }
}

extern "C" void kernel_launch(void* const* d_in, const int* in_sizes, int n_in,
                              void* d_out, int out_size) {
    const float4* ctrl = (const float4*)d_in[0];
    const float4* Nu   = (const float4*)d_in[1];
    const float4* Nv   = (const float4*)d_in[2];
    const int*    iu   = (const int*)d_in[3];
    const int*    iv   = (const int*)d_in[4];
    float*        out  = (float*)d_out;

    dim3 grid(OUT / V_TILE, OUT / U_TILE, BB);   // (4, 32, 64) = 8192 CTAs
    surfeval_kernel<<<grid, THREADS>>>(ctrl, Nu, Nv, iu, iv, out);
}

// round 14
// speedup vs baseline: 1.2196x; 1.2196x over previous
#include <cuda_runtime.h>
#include <cuda_bf16.h>

#define BB   64
#define MM   64
#define NN   64
#define OUT  512

#define U_TILE  32
#define V_TILE  128
#define THREADS 128

__global__ __launch_bounds__(THREADS) void surfeval_kernel(
    const float4* __restrict__ ctrl4,   // (B, M, N) float4 (xyzw)
    const float4* __restrict__ Nu4,     // (OUT)
    const float4* __restrict__ Nv4,     // (OUT)
    const int* __restrict__ iu,         // (OUT,4) int32
    const int* __restrict__ iv,         // (OUT,4) int32
    float* __restrict__ out)            // (B, OUT, OUT, 3)
{
    __shared__ float4 s_Nu[U_TILE];
    __shared__ int    s_row0[U_TILE];

    const int tid  = threadIdx.x;
    const int lane = tid & 31;
    const int wrp  = tid >> 5;
    const int vt   = blockIdx.x;
    const int ut   = blockIdx.y;
    const int b    = blockIdx.z;

    const int u_lo = ut * U_TILE;
    const int u_hi = u_lo + U_TILE;

    if (tid < U_TILE) {
        s_Nu[tid]   = __ldg(&Nu4[u_lo + tid]);
        s_row0[tid] = __ldg(&iu[(u_lo + tid) * 4]);
    }
    __syncthreads();

    const int v = vt * V_TILE + tid;
    const float4 nv = __ldg(&Nv4[v]);
    const int iv0 = __ldg(&iv[v * 4]);

    const float4* cb = ctrl4 + ((size_t)b * MM * NN) + iv0;

    // dense-store lane mapping: for k-th 128B line of this warp's 384B row,
    // lane stores float f = 32k+lane  ->  component c_k of point p_k
    const int f0 = lane,      p0 = f0 / 3, c0 = f0 - 3 * p0;
    const int f1 = 32 + lane, p1 = f1 / 3, c1 = f1 - 3 * p1;
    const int f2 = 64 + lane, p2 = f2 / 3, c2 = f2 - 3 * p2;

    // warp-cooperative store base: 96 floats per warp-row, contiguous
    float* wrow = out + (((size_t)b * OUT + u_lo) * OUT + (vt * V_TILE + wrp * 32)) * 3;
    const size_t u_stride = (size_t)OUT * 3;

    int u = u_lo;
    #pragma unroll 1
    while (u < u_hi) {
        const int row0 = s_row0[u - u_lo];

        float4 rd0, rd1, rd2, rd3;
        {
            const float4* p = cb + (size_t)row0 * NN;
            float4 a0 = p[0], a1 = p[1], a2 = p[2], a3 = p[3];
            rd0.x = nv.x*a0.x + nv.y*a1.x + nv.z*a2.x + nv.w*a3.x;
            rd0.y = nv.x*a0.y + nv.y*a1.y + nv.z*a2.y + nv.w*a3.y;
            rd0.z = nv.x*a0.z + nv.y*a1.z + nv.z*a2.z + nv.w*a3.z;
            rd0.w = nv.x*a0.w + nv.y*a1.w + nv.z*a2.w + nv.w*a3.w;
            p += NN;
            a0 = p[0]; a1 = p[1]; a2 = p[2]; a3 = p[3];
            rd1.x = nv.x*a0.x + nv.y*a1.x + nv.z*a2.x + nv.w*a3.x;
            rd1.y = nv.x*a0.y + nv.y*a1.y + nv.z*a2.y + nv.w*a3.y;
            rd1.z = nv.x*a0.z + nv.y*a1.z + nv.z*a2.z + nv.w*a3.z;
            rd1.w = nv.x*a0.w + nv.y*a1.w + nv.z*a2.w + nv.w*a3.w;
            p += NN;
            a0 = p[0]; a1 = p[1]; a2 = p[2]; a3 = p[3];
            rd2.x = nv.x*a0.x + nv.y*a1.x + nv.z*a2.x + nv.w*a3.x;
            rd2.y = nv.x*a0.y + nv.y*a1.y + nv.z*a2.y + nv.w*a3.y;
            rd2.z = nv.x*a0.z + nv.y*a1.z + nv.z*a2.z + nv.w*a3.z;
            rd2.w = nv.x*a0.w + nv.y*a1.w + nv.z*a2.w + nv.w*a3.w;
            p += NN;
            a0 = p[0]; a1 = p[1]; a2 = p[2]; a3 = p[3];
            rd3.x = nv.x*a0.x + nv.y*a1.x + nv.z*a2.x + nv.w*a3.x;
            rd3.y = nv.x*a0.y + nv.y*a1.y + nv.z*a2.y + nv.w*a3.y;
            rd3.z = nv.x*a0.z + nv.y*a1.z + nv.z*a2.z + nv.w*a3.z;
            rd3.w = nv.x*a0.w + nv.y*a1.w + nv.z*a2.w + nv.w*a3.w;
        }

        #pragma unroll 1
        do {
            const float4 nu = s_Nu[u - u_lo];
            float4 acc;
            acc.x = nu.x*rd0.x + nu.y*rd1.x + nu.z*rd2.x + nu.w*rd3.x;
            acc.y = nu.x*rd0.y + nu.y*rd1.y + nu.z*rd2.y + nu.w*rd3.y;
            acc.z = nu.x*rd0.z + nu.y*rd1.z + nu.z*rd2.z + nu.w*rd3.z;
            acc.w = nu.x*rd0.w + nu.y*rd1.w + nu.z*rd2.w + nu.w*rd3.w;

            const float inv = __fdividef(1.0f, acc.w);
            const float sx = acc.x * inv;
            const float sy = acc.y * inv;
            const float sz = acc.z * inv;

            // shuffle-transpose: 3 dense STG.32 (1 line each) instead of
            // 3 scattered STG.32 (3 lines each)
            {
                float gx = __shfl_sync(0xffffffffu, sx, p0);
                float gy = __shfl_sync(0xffffffffu, sy, p0);
                float gz = __shfl_sync(0xffffffffu, sz, p0);
                wrow[f0] = (c0 == 0) ? gx : ((c0 == 1) ? gy : gz);

                gx = __shfl_sync(0xffffffffu, sx, p1);
                gy = __shfl_sync(0xffffffffu, sy, p1);
                gz = __shfl_sync(0xffffffffu, sz, p1);
                wrow[f1] = (c1 == 0) ? gx : ((c1 == 1) ? gy : gz);

                gx = __shfl_sync(0xffffffffu, sx, p2);
                gy = __shfl_sync(0xffffffffu, sy, p2);
                gz = __shfl_sync(0xffffffffu, sz, p2);
                wrow[f2] = (c2 == 0) ? gx : ((c2 == 1) ? gy : gz);
            }

            wrow += u_stride;
            ++u;
        } while (u < u_hi && s_row0[u - u_lo] == row0);
    }
}

extern "C" void kernel_launch(void* const* d_in, const int* in_sizes, int n_in,
                              void* d_out, int out_size) {
    const float4* ctrl = (const float4*)d_in[0];
    const float4* Nu   = (const float4*)d_in[1];
    const float4* Nv   = (const float4*)d_in[2];
    const int*    iu   = (const int*)d_in[3];
    const int*    iv   = (const int*)d_in[4];
    float*        out  = (float*)d_out;

    dim3 grid(OUT / V_TILE, OUT / U_TILE, BB);   // (4, 16, 64) = 4096 CTAs
    surfeval_kernel<<<grid, THREADS>>>(ctrl, Nu, Nv, iu, iv, out);
}